// round 9
// baseline (speedup 1.0000x reference)
#include <cuda_runtime.h>
#include <cstdint>

// Internal heap nodes, heap-indexed: g_tree[i] for i in [1, 2^19).
// Levels 0..18 are materialized (levels 0..11 by the build tail-block).
// Levels 19..24 + the priority are reconstructed in registers from a 256B
// leaf burst. All sums use the identical left+right pairing as the
// reference's reshape(-1,2).sum(axis=1), so every comparison is bitwise-exact.
#define BOUND (1 << 24)
__device__ float g_tree[1 << 19];          // 2 MB
__device__ unsigned int g_cnt = 0;         // "last block" counter (self-resetting)

// ---------------------------------------------------------------------------
// Build: each block reduces 4096 contiguous leaves; stores levels 18..12 only.
// The LAST block to finish additionally builds levels 11..0 directly in
// global memory (no big smem => no occupancy penalty for the other blocks).
// ---------------------------------------------------------------------------
__global__ __launch_bounds__(256) void build_lower(const float* __restrict__ leaf) {
    const int b = blockIdx.x;           // 4096 blocks
    const int t = threadIdx.x;
    const int lane = t & 31;
    const int w = t >> 5;               // 8 warps
    __shared__ float s17[32];
    __shared__ bool isLast;

    const float4* __restrict__ in = reinterpret_cast<const float4*>(leaf) + (size_t)b * 1024;

    float* g18 = g_tree + (1u << 18) + (size_t)b * 64;
    float* g17 = g_tree + (1u << 17) + (size_t)b * 32;

#pragma unroll
    for (int r = 0; r < 4; ++r) {
        const int q = r * 256 + t;                    // level-22 node id in block
        float4 a = in[q];                             // coalesced LDG.128
        float v = (a.x + a.y) + (a.z + a.w);          // level-22 value (exact pairing)
        float u;
        u = __shfl_down_sync(0xffffffffu, v, 1);  v += u;   // level 21
        u = __shfl_down_sync(0xffffffffu, v, 2);  v += u;   // level 20
        u = __shfl_down_sync(0xffffffffu, v, 4);  v += u;   // level 19
        u = __shfl_down_sync(0xffffffffu, v, 8);  v += u;   // level 18
        if (!(lane & 15)) g18[r * 16 + w * 2 + (lane >> 4)] = v;
        u = __shfl_down_sync(0xffffffffu, v, 16); v += u;   // level 17
        if (lane == 0) { g17[r * 8 + w] = v; s17[r * 8 + w] = v; }
    }
    __syncthreads();

    if (w == 0) {
        float v = s17[lane];
        float u;
        float* g16 = g_tree + (1u << 16) + (size_t)b * 16;
        float* g15 = g_tree + (1u << 15) + (size_t)b * 8;
        float* g14 = g_tree + (1u << 14) + (size_t)b * 4;
        float* g13 = g_tree + (1u << 13) + (size_t)b * 2;
        float* g12 = g_tree + (1u << 12) + (size_t)b;
        u = __shfl_down_sync(0xffffffffu, v, 1);  v += u;
        if (!(lane & 1))  g16[lane >> 1] = v;
        u = __shfl_down_sync(0xffffffffu, v, 2);  v += u;
        if (!(lane & 3))  g15[lane >> 2] = v;
        u = __shfl_down_sync(0xffffffffu, v, 4);  v += u;
        if (!(lane & 7))  g14[lane >> 3] = v;
        u = __shfl_down_sync(0xffffffffu, v, 8);  v += u;
        if (!(lane & 15)) g13[lane >> 4] = v;
        u = __shfl_down_sync(0xffffffffu, v, 16); v += u;
        if (lane == 0)    g12[0] = v;
    }

    // ---- tail: last finished block builds levels 11..0 in g_tree[1..4096) ----
    __threadfence();
    __syncthreads();
    if (t == 0) isLast = (atomicAdd(&g_cnt, 1u) == gridDim.x - 1u);
    __syncthreads();
    if (!isLast) return;

#pragma unroll
    for (int n = 2048; n >= 1; n >>= 1) {
        for (int i = t; i < n; i += 256)
            g_tree[n + i] = g_tree[2 * (n + i)] + g_tree[2 * (n + i) + 1];
        __syncthreads();   // orders global writes/reads within the block
    }
    if (t == 0) g_cnt = 0;   // reset for next graph replay
}

// ---------------------------------------------------------------------------
// Descend: no shared memory, no barriers. Levels 1..12: six 2-level rounds
// (L1-resident 32 KB region). Levels 13..18: two 3-level rounds with
// vectorized speculative loads. Then one 256B burst of the 64 leaves under
// the level-18 node resolves levels 19..24 AND the priority in registers
// (exact reference pairing). 512 blocks x 128 threads: all SMs engaged.
// ---------------------------------------------------------------------------
__global__ __launch_bounds__(128) void descend(const float* __restrict__ leaf,
                                               const float* __restrict__ frac,
                                               float* __restrict__ out,
                                               int batch) {
    const int q = blockIdx.x * 128 + threadIdx.x;
    if (q >= batch) return;

    float v = frac[q] * __ldg(&g_tree[1]);
    int idx = 1;

    // Levels 1..12: six 2-level rounds.
#pragma unroll
    for (int d = 0; d < 6; ++d) {
        float a = __ldg(&g_tree[2 * idx]);
        float4 bb = __ldg(reinterpret_cast<const float4*>(&g_tree[4 * idx]));
        bool r1 = (a < v);   v = r1 ? (v - a) : v;
        float l2 = r1 ? bb.z : bb.x;          // tree[4i+2] / tree[4i]
        bool r2 = (l2 < v);  v = r2 ? (v - l2) : v;
        idx = 4 * idx + 2 * (int)r1 + (int)r2;
    }

    // Levels 13..18: two 3-level rounds.
#pragma unroll
    for (int round = 0; round < 2; ++round) {
        float a = __ldg(&g_tree[2 * idx]);
        float4 bb = __ldg(reinterpret_cast<const float4*>(&g_tree[4 * idx]));
        float4 c0 = __ldg(reinterpret_cast<const float4*>(&g_tree[8 * idx]));
        float4 c1 = __ldg(reinterpret_cast<const float4*>(&g_tree[8 * idx + 4]));
        bool r1 = (a < v);   v = r1 ? (v - a) : v;
        float l2 = r1 ? bb.z : bb.x;
        bool r2 = (l2 < v);  v = r2 ? (v - l2) : v;
        float l3 = r1 ? (r2 ? c1.z : c1.x) : (r2 ? c0.z : c0.x);
        bool r3 = (l3 < v);  v = r3 ? (v - l3) : v;
        idx = 8 * idx + 4 * (int)r1 + 2 * (int)r2 + (int)r3;
    }

    // idx at level 18. Burst the 64 leaves under it (256B aligned, 4 lines).
    const int base = (idx << 6) - BOUND;
    const float4* lp = reinterpret_cast<const float4*>(leaf + base);
    float4 L[16];
#pragma unroll
    for (int j = 0; j < 16; ++j) L[j] = __ldg(lp + j);

    // Rebuild levels 23..19 sums with exact pairing; keep left-children only.
    float s23e[16], s22[16];
#pragma unroll
    for (int j = 0; j < 16; ++j) {
        float a = L[j].x + L[j].y;        // s23[2j]
        float bq = L[j].z + L[j].w;       // s23[2j+1]
        s23e[j] = a;
        s22[j] = a + bq;
    }
    float s22e[8], s21[8];
#pragma unroll
    for (int k = 0; k < 8; ++k) { s22e[k] = s22[2 * k]; s21[k] = s22[2 * k] + s22[2 * k + 1]; }
    float s21e[4], s20[4];
#pragma unroll
    for (int m = 0; m < 4; ++m) { s21e[m] = s21[2 * m]; s20[m] = s21[2 * m] + s21[2 * m + 1]; }
    float s19_0 = s20[0] + s20[1];

    // Level 19.
    bool b0 = (s19_0 < v); v = b0 ? (v - s19_0) : v;
    // Narrow the 16 float4s by b0 (frees half the liveness).
    float4 M[8];
#pragma unroll
    for (int j = 0; j < 8; ++j) M[j] = b0 ? L[8 + j] : L[j];

    // Level 20.
    float l20 = b0 ? s20[2] : s20[0];
    bool b1 = (l20 < v); v = b1 ? (v - l20) : v;
    float4 N[4];
#pragma unroll
    for (int j = 0; j < 4; ++j) N[j] = b1 ? M[4 + j] : M[j];

    // Level 21.
    float l21 = b0 ? (b1 ? s21e[3] : s21e[2]) : (b1 ? s21e[1] : s21e[0]);
    bool b2 = (l21 < v); v = b2 ? (v - l21) : v;
    float4 O0 = b2 ? N[2] : N[0];
    float4 O1 = b2 ? N[3] : N[1];

    // Level 22: s22e[4b0+2b1+b2].
    float t0 = b2 ? s22e[1] : s22e[0];
    float t1 = b2 ? s22e[3] : s22e[2];
    float t2 = b2 ? s22e[5] : s22e[4];
    float t3 = b2 ? s22e[7] : s22e[6];
    float l22 = b0 ? (b1 ? t3 : t2) : (b1 ? t1 : t0);
    bool b3 = (l22 < v); v = b3 ? (v - l22) : v;
    float4 F = b3 ? O1 : O0;

    // Level 23: s23e[8b0+4b1+2b2+b3].
    float u0 = b3 ? s23e[1]  : s23e[0];
    float u1 = b3 ? s23e[3]  : s23e[2];
    float u2 = b3 ? s23e[5]  : s23e[4];
    float u3 = b3 ? s23e[7]  : s23e[6];
    float u4 = b3 ? s23e[9]  : s23e[8];
    float u5 = b3 ? s23e[11] : s23e[10];
    float u6 = b3 ? s23e[13] : s23e[12];
    float u7 = b3 ? s23e[15] : s23e[14];
    float w0 = b2 ? u1 : u0;
    float w1 = b2 ? u3 : u2;
    float w2 = b2 ? u5 : u4;
    float w3 = b2 ? u7 : u6;
    float l23 = b0 ? (b1 ? w3 : w2) : (b1 ? w1 : w0);
    bool b4 = (l23 < v); v = b4 ? (v - l23) : v;

    // Level 24 (leaf decision) + priority from the selected float4.
    float e0 = b4 ? F.z : F.x;
    float e1 = b4 ? F.w : F.y;
    bool b5 = (e0 < v);
    float prio = b5 ? e1 : e0;

    const int leafIdx = base + 32 * (int)b0 + 16 * (int)b1 + 8 * (int)b2
                             + 4 * (int)b3 + 2 * (int)b4 + (int)b5;
    out[q] = (float)leafIdx;      // exact in f32 (< 2^24)
    out[batch + q] = prio;
}

extern "C" void kernel_launch(void* const* d_in, const int* in_sizes, int n_in,
                              void* d_out, int out_size) {
    const float* leaf = (const float*)d_in[0];
    const float* frac = (const float*)d_in[1];
    float* out = (float*)d_out;
    const int batch = in_sizes[1];

    build_lower<<<BOUND / 4096, 256>>>(leaf);
    descend<<<(batch + 127) / 128, 128>>>(leaf, frac, out, batch);
}

// round 10
// speedup vs baseline: 1.0717x; 1.0717x over previous
#include <cuda_runtime.h>
#include <cstdint>

// Internal heap nodes, heap-indexed: g_tree[i] for i in [1, 2^21).
// build_lower stores levels 12..20; build_top (1 block) stores levels 0..11.
// Levels 21..23 are recomputed in registers from a 64B leaf burst. All sums
// use the identical left+right pairing as the reference's
// reshape(-1,2).sum(axis=1), so every comparison is bitwise-exact.
#define BOUND (1 << 24)
__device__ float g_tree[1 << 21];   // 8 MB

// ---------------------------------------------------------------------------
// Build: each block reduces 4096 contiguous leaves; stores levels 20..12.
// No fences, no atomics, no oversized smem (those cost ~6 us in R7/R9).
// ---------------------------------------------------------------------------
__global__ __launch_bounds__(256) void build_lower(const float* __restrict__ leaf) {
    const int b = blockIdx.x;           // 4096 blocks
    const int t = threadIdx.x;
    const int lane = t & 31;
    const int w = t >> 5;               // 8 warps
    __shared__ float s17[32];

    const float4* __restrict__ in = reinterpret_cast<const float4*>(leaf) + (size_t)b * 1024;

    float* g20 = g_tree + (1u << 20) + (size_t)b * 256;
    float* g19 = g_tree + (1u << 19) + (size_t)b * 128;
    float* g18 = g_tree + (1u << 18) + (size_t)b * 64;
    float* g17 = g_tree + (1u << 17) + (size_t)b * 32;

#pragma unroll
    for (int r = 0; r < 4; ++r) {
        const int q = r * 256 + t;                    // level-22 node id in block
        float4 a = in[q];                             // coalesced LDG.128
        float v = (a.x + a.y) + (a.z + a.w);          // level-22 value (exact pairing)
        float u;
        u = __shfl_down_sync(0xffffffffu, v, 1);  v += u;   // level 21 (not stored)
        u = __shfl_down_sync(0xffffffffu, v, 2);  v += u;   // level 20
        if (!(lane & 3))  g20[r * 64 + w * 8 + (lane >> 2)] = v;
        u = __shfl_down_sync(0xffffffffu, v, 4);  v += u;   // level 19
        if (!(lane & 7))  g19[r * 32 + w * 4 + (lane >> 3)] = v;
        u = __shfl_down_sync(0xffffffffu, v, 8);  v += u;   // level 18
        if (!(lane & 15)) g18[r * 16 + w * 2 + (lane >> 4)] = v;
        u = __shfl_down_sync(0xffffffffu, v, 16); v += u;   // level 17
        if (lane == 0) { g17[r * 8 + w] = v; s17[r * 8 + w] = v; }
    }
    __syncthreads();

    if (w == 0) {
        float v = s17[lane];
        float u;
        float* g16 = g_tree + (1u << 16) + (size_t)b * 16;
        float* g15 = g_tree + (1u << 15) + (size_t)b * 8;
        float* g14 = g_tree + (1u << 14) + (size_t)b * 4;
        float* g13 = g_tree + (1u << 13) + (size_t)b * 2;
        float* g12 = g_tree + (1u << 12) + (size_t)b;
        u = __shfl_down_sync(0xffffffffu, v, 1);  v += u;
        if (!(lane & 1))  g16[lane >> 1] = v;
        u = __shfl_down_sync(0xffffffffu, v, 2);  v += u;
        if (!(lane & 3))  g15[lane >> 2] = v;
        u = __shfl_down_sync(0xffffffffu, v, 4);  v += u;
        if (!(lane & 7))  g14[lane >> 3] = v;
        u = __shfl_down_sync(0xffffffffu, v, 8);  v += u;
        if (!(lane & 15)) g13[lane >> 4] = v;
        u = __shfl_down_sync(0xffffffffu, v, 16); v += u;
        if (lane == 0)    g12[0] = v;
    }
}

// ---------------------------------------------------------------------------
// build_top: 1 block, 1024 threads. Reads level 12 (heap [4096, 8192)),
// reduces in smem, stores levels 11..0 into g_tree[1..4096).
// ---------------------------------------------------------------------------
__global__ __launch_bounds__(1024) void build_top() {
    __shared__ float s[8192];
    const int t = threadIdx.x;
    float4* s4p = reinterpret_cast<float4*>(s);
    const float4* g4 = reinterpret_cast<const float4*>(g_tree);
    for (int i = t; i < 1024; i += 1024) s4p[1024 + i] = g4[1024 + i];
    if (t == 0) s[0] = 0.0f;
    __syncthreads();
#pragma unroll
    for (int n = 2048; n >= 1; n >>= 1) {
        for (int i = t; i < n; i += 1024)
            s[n + i] = s[2 * (n + i)] + s[2 * (n + i) + 1];
        __syncthreads();
    }
    // Store heap [0, 4096) (slot 0 is the zeroed dummy) via float4.
    float4* g4w = reinterpret_cast<float4*>(g_tree);
    for (int i = t; i < 1024; i += 1024) g4w[i] = s4p[i];
}

// ---------------------------------------------------------------------------
// Descend: minimize divergent global loads (L1tex wavefronts are the
// bottleneck). Stage prebuilt levels 0..12 (32 KB) with ONE coalesced copy +
// one barrier; 12 decisions in smem (bank-conflict cost ~4 cyc vs ~64 cyc for
// a divergent L1 gather). Levels 13..20: four 2-level rounds = 8 divergent
// loads (1 per level, the minimum). Levels 21..24 + priority from one 64B
// leaf burst (4 loads). 12 divergent loads/query total vs 20 in R7.
// ---------------------------------------------------------------------------
__global__ __launch_bounds__(256) void descend(const float* __restrict__ leaf,
                                               const float* __restrict__ frac,
                                               float* __restrict__ out,
                                               int batch) {
    __shared__ float s[8192];
    const int t = threadIdx.x;
    const int q = blockIdx.x * 256 + t;
    const float f = (q < batch) ? frac[q] : 0.0f;   // overlap with staging

    {   // stage heap [0, 8192): levels 0..12, all prebuilt
        float4* s4p = reinterpret_cast<float4*>(s);
        const float4* g4 = reinterpret_cast<const float4*>(g_tree);
#pragma unroll
        for (int i = t; i < 2048; i += 256) s4p[i] = g4[i];
    }
    __syncthreads();

    if (q >= batch) return;

    float v = f * s[1];
    int idx = 1;

    // Levels 1..12: smem decisions.
#pragma unroll
    for (int d = 0; d < 12; ++d) {
        idx <<= 1;
        float l = s[idx];
        bool r = (l < v);
        v = r ? (v - l) : v;
        idx += (int)r;
    }

    // Levels 13..20: four 2-level rounds (scalar + one float4 per round).
#pragma unroll
    for (int d = 0; d < 4; ++d) {
        float a = __ldg(&g_tree[2 * idx]);
        float4 bb = __ldg(reinterpret_cast<const float4*>(&g_tree[4 * idx]));
        bool r1 = (a < v);   v = r1 ? (v - a) : v;
        float l2 = r1 ? bb.z : bb.x;          // tree[4i+2] / tree[4i]
        bool r2 = (l2 < v);  v = r2 ? (v - l2) : v;
        idx = 4 * idx + 2 * (int)r1 + (int)r2;
    }

    // idx at level 20. Burst the 16 leaves under it (64B aligned, 1 line).
    const int base = (idx << 4) - BOUND;
    const float4* lp = reinterpret_cast<const float4*>(leaf + base);
    float4 A = __ldg(lp);
    float4 B = __ldg(lp + 1);
    float4 C = __ldg(lp + 2);
    float4 D = __ldg(lp + 3);

    float s8_0 = A.x + A.y, s8_2 = B.x + B.y;
    float s8_4 = C.x + C.y, s8_6 = D.x + D.y;
    float s4_0 = s8_0 + (A.z + A.w), s4_1 = s8_2 + (B.z + B.w);
    float s4_2 = s8_4 + (C.z + C.w);
    float s2_0 = s4_0 + s4_1;

    bool r1 = (s2_0 < v); v = r1 ? (v - s2_0) : v;          // level 21
    float l22 = r1 ? s4_2 : s4_0;
    bool r2 = (l22 < v);  v = r2 ? (v - l22) : v;           // level 22
    float l23 = r1 ? (r2 ? s8_6 : s8_4) : (r2 ? s8_2 : s8_0);
    bool r3 = (l23 < v);  v = r3 ? (v - l23) : v;           // level 23
    float4 P = r1 ? C : A;
    float4 Q = r1 ? D : B;
    float4 R = r2 ? Q : P;
    float e0 = r3 ? R.z : R.x;
    float e1 = r3 ? R.w : R.y;
    bool r4 = (e0 < v);                                     // level 24
    float prio = r4 ? e1 : e0;

    const int leafIdx = base + 8 * (int)r1 + 4 * (int)r2 + 2 * (int)r3 + (int)r4;
    out[q] = (float)leafIdx;      // exact in f32 (< 2^24)
    out[batch + q] = prio;
}

extern "C" void kernel_launch(void* const* d_in, const int* in_sizes, int n_in,
                              void* d_out, int out_size) {
    const float* leaf = (const float*)d_in[0];
    const float* frac = (const float*)d_in[1];
    float* out = (float*)d_out;
    const int batch = in_sizes[1];

    build_lower<<<BOUND / 4096, 256>>>(leaf);
    build_top<<<1, 1024>>>();
    descend<<<(batch + 255) / 256, 256>>>(leaf, frac, out, batch);
}